// round 2
// baseline (speedup 1.0000x reference)
#include <cuda_runtime.h>
#include <cuda_bf16.h>
#include <cstdint>

typedef unsigned long long ull;

#define NPTS   10000
#define NPAD   10016
#define DDIM   3072
#define NSLOT  16
#define GRID1  148
#define KCH    96          // k-chunks of 32 in k1
#define TILES1 20          // n-tiles of 512 in k1
#define ITEMS1 (TILES1*KCH)   // 1920
#define TILES3 96          // d-tiles of 32 in k3
#define NCH3   10          // n-chunks of 1000 in k3
#define ITEMS3 (TILES3*NCH3)  // 960

// ---------------- device scratch (no allocation APIs allowed) ----------------
__device__ __align__(16) float g_cp[NSLOT * 16 * NPAD];  // cross partials [slot][b][n]
__device__ __align__(16) float g_ip[NSLOT * NPAD];       // ||img||^2 partials [slot][n]
__device__ __align__(16) float g_w [NPAD * 16];          // weights packed [n][b]
__device__ __align__(16) float g_mp[NSLOT * 16 * DDIM];  // mix partials [slot][b][d]
__device__ __align__(16) float g_xt[DDIM * 16];          // x transposed [k][b]

// ---------------- packed f32x2 helpers ----------------
__device__ __forceinline__ ull dup2(float v) {
    ull r; asm("mov.b64 %0, {%1, %1};" : "=l"(r) : "f"(v)); return r;
}
__device__ __forceinline__ void fma2(ull& d, ull a, ull b) {
    asm("fma.rn.f32x2 %0, %1, %2, %0;" : "+l"(d) : "l"(a), "l"(b));
}
__device__ __forceinline__ void unpack2(ull v, float& lo, float& hi) {
    asm("mov.b64 {%0, %1}, %2;" : "=f"(lo), "=f"(hi) : "l"(v));
}

// ---------------- K0: zero slot buffers + transpose x ----------------
// zero counts (in float4): g_cp 641024, g_ip 40064, g_mp 196608  -> 877696
#define Z_CP 641024
#define Z_IP 40064
#define Z_MP 196608
#define Z_TOT (Z_CP + Z_IP + Z_MP)

__global__ __launch_bounds__(256) void kzero(const float* __restrict__ x) {
    int i = blockIdx.x * 256 + threadIdx.x;
    float4 z = make_float4(0.f, 0.f, 0.f, 0.f);
    if (i < Z_CP)                ((float4*)g_cp)[i] = z;
    else if (i < Z_CP + Z_IP)    ((float4*)g_ip)[i - Z_CP] = z;
    else if (i < Z_TOT)          ((float4*)g_mp)[i - Z_CP - Z_IP] = z;
    if (i < DDIM * 16) {         // transpose x: g_xt[k*16+b] = x[b*3072+k]
        int b = i & 15, k = i >> 4;
        g_xt[i] = x[b * DDIM + k];
    }
}

// ---------------- K1: cross[b][n] = x[b]·img[n] and ||img_n||^2 ----------------
// items = (n-tile of 512) x (k-chunk of 32), tile-major; 148 CTAs, 256 thr.
// Thread t owns rows n_a = tile*512+t and n_b = n_a+256, all 16 b packed in pairs.
__global__ __launch_bounds__(256) void k1(const float* __restrict__ img) {
    const int t = threadIdx.x, c = blockIdx.x;
    const int lo = (c * ITEMS1) / GRID1;
    const int hi = ((c + 1) * ITEMS1) / GRID1;
    const int slot = c & (NSLOT - 1);

    ull aa[8], ab[8];
    float qa = 0.f, qb = 0.f;
#pragma unroll
    for (int j = 0; j < 8; j++) { aa[j] = 0ULL; ab[j] = 0ULL; }
    int cur = lo / KCH;

    for (int w = lo; w < hi; w++) {
        int tile = w / KCH, ch = w - tile * KCH;
        if (tile != cur) {
            // flush cur
            int fa = cur * 512 + t, fb = fa + 256;
            if (fa < NPTS) {
#pragma unroll
                for (int bp = 0; bp < 8; bp++) {
                    float l, h; unpack2(aa[bp], l, h);
                    g_cp[(slot * 16 + 2 * bp) * NPAD + fa] = l;
                    g_cp[(slot * 16 + 2 * bp + 1) * NPAD + fa] = h;
                }
                g_ip[slot * NPAD + fa] = qa;
            }
            if (fb < NPTS) {
#pragma unroll
                for (int bp = 0; bp < 8; bp++) {
                    float l, h; unpack2(ab[bp], l, h);
                    g_cp[(slot * 16 + 2 * bp) * NPAD + fb] = l;
                    g_cp[(slot * 16 + 2 * bp + 1) * NPAD + fb] = h;
                }
                g_ip[slot * NPAD + fb] = qb;
            }
#pragma unroll
            for (int j = 0; j < 8; j++) { aa[j] = 0ULL; ab[j] = 0ULL; }
            qa = 0.f; qb = 0.f;
            cur = tile;
        }
        const int na = tile * 512 + t, nb = na + 256;
        const int k0 = ch * 32;
        const bool ga = na < NPTS, gb = nb < NPTS;
        const float4* pa = (const float4*)(img + (size_t)na * DDIM + k0);
        const float4* pb = (const float4*)(img + (size_t)nb * DDIM + k0);
        const ulonglong2* xt = (const ulonglong2*)(g_xt + (size_t)k0 * 16);
        const float4 z4 = make_float4(0.f, 0.f, 0.f, 0.f);
#pragma unroll
        for (int q = 0; q < 8; q++) {
            float4 ia = ga ? pa[q] : z4;
            float4 ib = gb ? pb[q] : z4;
#pragma unroll
            for (int kk = 0; kk < 4; kk++) {
                float va = ((const float*)&ia)[kk];
                float vb = ((const float*)&ib)[kk];
                qa = fmaf(va, va, qa);
                qb = fmaf(vb, vb, qb);
                ull da = dup2(va), db = dup2(vb);
                const ulonglong2* xr = xt + (size_t)(q * 4 + kk) * 4;
#pragma unroll
                for (int j = 0; j < 4; j++) {
                    ulonglong2 u = xr[j];   // b pairs (4j,4j+1),(4j+2,4j+3)
                    fma2(aa[2 * j],     u.x, da);
                    fma2(aa[2 * j + 1], u.y, da);
                    fma2(ab[2 * j],     u.x, db);
                    fma2(ab[2 * j + 1], u.y, db);
                }
            }
        }
    }
    // final flush
    {
        int fa = cur * 512 + t, fb = fa + 256;
        if (fa < NPTS) {
#pragma unroll
            for (int bp = 0; bp < 8; bp++) {
                float l, h; unpack2(aa[bp], l, h);
                g_cp[(slot * 16 + 2 * bp) * NPAD + fa] = l;
                g_cp[(slot * 16 + 2 * bp + 1) * NPAD + fa] = h;
            }
            g_ip[slot * NPAD + fa] = qa;
        }
        if (fb < NPTS) {
#pragma unroll
            for (int bp = 0; bp < 8; bp++) {
                float l, h; unpack2(ab[bp], l, h);
                g_cp[(slot * 16 + 2 * bp) * NPAD + fb] = l;
                g_cp[(slot * 16 + 2 * bp + 1) * NPAD + fb] = h;
            }
            g_ip[slot * NPAD + fb] = qb;
        }
    }
}

// ---------------- K2: softmax over n, write packed weights [n][b] ----------------
__global__ __launch_bounds__(256) void k2(const float* __restrict__ sval) {
    const int t = threadIdx.x, b = blockIdx.x;
    const float s0 = sval[0];
    const float bt2 = s0;
    const float at = sqrtf(1.f - s0);
    const float c1 = at / bt2;
    const float c2 = -(at * at) / (2.f * bt2);

    __shared__ float rbuf[8];
    __shared__ float bcast;

    float4 av[10];
    float m = -1e30f;
    int it = 0;
    for (int i = t; i < 2500; i += 256, it++) {
        float4 cv = make_float4(0.f, 0.f, 0.f, 0.f);
        float4 qv = make_float4(0.f, 0.f, 0.f, 0.f);
#pragma unroll
        for (int s = 0; s < NSLOT; s++) {
            float4 u = *(const float4*)(g_cp + (size_t)(s * 16 + b) * NPAD + 4 * i);
            cv.x += u.x; cv.y += u.y; cv.z += u.z; cv.w += u.w;
            float4 v = *(const float4*)(g_ip + (size_t)s * NPAD + 4 * i);
            qv.x += v.x; qv.y += v.y; qv.z += v.z; qv.w += v.w;
        }
        float4 a;
        a.x = fmaf(c1, cv.x, c2 * qv.x);
        a.y = fmaf(c1, cv.y, c2 * qv.y);
        a.z = fmaf(c1, cv.z, c2 * qv.z);
        a.w = fmaf(c1, cv.w, c2 * qv.w);
        av[it] = a;
        m = fmaxf(m, fmaxf(fmaxf(a.x, a.y), fmaxf(a.z, a.w)));
    }
    const int nit = it;
    // block max reduce
    for (int o = 16; o; o >>= 1) m = fmaxf(m, __shfl_xor_sync(0xffffffffu, m, o));
    if ((t & 31) == 0) rbuf[t >> 5] = m;
    __syncthreads();
    if (t == 0) {
        float v = rbuf[0];
        for (int wv = 1; wv < 8; wv++) v = fmaxf(v, rbuf[wv]);
        bcast = v;
    }
    __syncthreads();
    const float M = bcast;
    __syncthreads();

    const float L2E = 1.44269504088896340736f;
    float sm = 0.f;
    for (int j = 0; j < nit; j++) {
        float4 a = av[j];
        a.x = exp2f((a.x - M) * L2E);
        a.y = exp2f((a.y - M) * L2E);
        a.z = exp2f((a.z - M) * L2E);
        a.w = exp2f((a.w - M) * L2E);
        av[j] = a;
        sm += a.x + a.y + a.z + a.w;
    }
    for (int o = 16; o; o >>= 1) sm += __shfl_xor_sync(0xffffffffu, sm, o);
    if ((t & 31) == 0) rbuf[t >> 5] = sm;
    __syncthreads();
    if (t == 0) {
        float v = 0.f;
        for (int wv = 0; wv < 8; wv++) v += rbuf[wv];
        bcast = v;
    }
    __syncthreads();
    const float inv = 1.f / bcast;

    it = 0;
    for (int i = t; i < 2500; i += 256, it++) {
        float4 a = av[it];
        int n = 4 * i;
        g_w[(n + 0) * 16 + b] = a.x * inv;
        g_w[(n + 1) * 16 + b] = a.y * inv;
        g_w[(n + 2) * 16 + b] = a.z * inv;
        g_w[(n + 3) * 16 + b] = a.w * inv;
    }
}

// ---------------- K3: mix[b][d] = sum_n w[n][b] img[n][d] ----------------
// items = (d-tile of 32) x (n-chunk of 1000), tile-major; 148 CTAs, 256 thr.
// thread = (partition p = t>>3 over n, dt = t&7 over d) owns 4 d-cols, 16 b.
__device__ __forceinline__ void flush3(ull (&acc)[8][4], float* red, int t,
                                       int tile, int slot) {
#pragma unroll 1
    for (int bp = 0; bp < 8; bp++) {
        __syncthreads();
        float* r = red + t * 8;
#pragma unroll
        for (int d = 0; d < 4; d++) {
            float l, h; unpack2(acc[bp][d], l, h);
            r[2 * d] = l; r[2 * d + 1] = h;
        }
        __syncthreads();
        if (t < 64) {
            int h = t & 1, d = (t >> 1) & 3, dtx = t >> 3;
            float s = 0.f;
#pragma unroll
            for (int pp = 0; pp < 32; pp++)
                s += red[(pp * 8 + dtx) * 8 + 2 * d + h];
            g_mp[(slot * 16 + 2 * bp + h) * DDIM + tile * 32 + dtx * 4 + d] = s;
        }
    }
}

__global__ __launch_bounds__(256) void k3(const float* __restrict__ img) {
    __shared__ float red[2048];
    const int t = threadIdx.x, c = blockIdx.x;
    const int lo = (c * ITEMS3) / GRID1;
    const int hi = ((c + 1) * ITEMS3) / GRID1;
    const int slot = c & (NSLOT - 1);
    const int p = t >> 3, dt = t & 7;

    ull acc[8][4];
#pragma unroll
    for (int i = 0; i < 8; i++)
#pragma unroll
        for (int j = 0; j < 4; j++) acc[i][j] = 0ULL;

    int cur = lo / NCH3;
    for (int w = lo; w < hi; w++) {
        int tile = w / NCH3, ch = w - tile * NCH3;
        if (tile != cur) {
            flush3(acc, red, t, cur, slot);
#pragma unroll
            for (int i = 0; i < 8; i++)
#pragma unroll
                for (int j = 0; j < 4; j++) acc[i][j] = 0ULL;
            cur = tile;
        }
        const int dbase = tile * 32 + dt * 4;
        const int nend = ch * 1000 + 1000;
        for (int n = ch * 1000 + p; n < nend; n += 32) {
            const ulonglong2* wr = (const ulonglong2*)(g_w + (size_t)n * 16);
            ulonglong2 u0 = wr[0], u1 = wr[1], u2 = wr[2], u3 = wr[3];
            ull wp[8] = { u0.x, u0.y, u1.x, u1.y, u2.x, u2.y, u3.x, u3.y };
            float4 iv = *(const float4*)(img + (size_t)n * DDIM + dbase);
#pragma unroll
            for (int d = 0; d < 4; d++) {
                ull dv = dup2(((const float*)&iv)[d]);
#pragma unroll
                for (int bp = 0; bp < 8; bp++)
                    fma2(acc[bp][d], wp[bp], dv);
            }
        }
    }
    flush3(acc, red, t, cur, slot);
}

// ---------------- K4: out = (at*mix - x)/bt2 ----------------
__global__ __launch_bounds__(256) void k4(const float* __restrict__ x,
                                          const float* __restrict__ sval,
                                          float* __restrict__ out) {
    int i = blockIdx.x * 256 + threadIdx.x;
    if (i >= 16 * DDIM) return;
    const float s0 = sval[0];
    const float bt2 = s0;
    const float at = sqrtf(1.f - s0);
    float mix = 0.f;
#pragma unroll
    for (int s = 0; s < NSLOT; s++) mix += g_mp[s * 16 * DDIM + i];
    out[i] = (at * mix - x[i]) / bt2;
}

// ---------------- launch ----------------
extern "C" void kernel_launch(void* const* d_in, const int* in_sizes, int n_in,
                              void* d_out, int out_size) {
    const float* x    = (const float*)d_in[0];
    const float* img  = (const float*)d_in[1];
    const float* sval = (const float*)d_in[2];
    float* out = (float*)d_out;

    kzero<<<(Z_TOT + 255) / 256, 256>>>(x);
    k1<<<GRID1, 256>>>(img);
    k2<<<16, 256>>>(sval);
    k3<<<GRID1, 256>>>(img);
    k4<<<(16 * DDIM + 255) / 256, 256>>>(x, sval, out);
}

// round 3
// speedup vs baseline: 1.3928x; 1.3928x over previous
#include <cuda_runtime.h>
#include <cuda_bf16.h>
#include <cstdint>

typedef unsigned long long ull;

#define NPTS  10000
#define NPAD  10016
#define DDIM  3072
#define NSLOT 16
#define GRID  148

// k1: n-tiles of 512  x  k-chunks of 16
#define K1_TILES 20
#define K1_KCH   192
#define K1_ITEMS (K1_TILES * K1_KCH)   // 3840
#define XS_STRIDE 20                   // floats per smem row: 16B-aligned, 4-wf LDS.128

// k3: d-tiles of 32  x  n-chunks of 1000
#define K3_TILES 96
#define K3_NCH   10
#define K3_ITEMS (K3_TILES * K3_NCH)   // 960

// ---------------- device scratch ----------------
__device__ __align__(16) float g_cp[NSLOT * 16 * NPAD];  // cross partials [slot][b][n]
__device__ __align__(16) float g_ip[NSLOT * NPAD];       // ||img||^2 partials [slot][n]
__device__ __align__(16) float g_lg[16 * NPAD];          // logits [b][n]
__device__ __align__(16) float g_w [NPAD * 16];          // weights packed [n][b]
__device__ __align__(16) float g_mp[NSLOT * 16 * DDIM];  // mix partials [slot][b][d]
__device__ __align__(16) float g_xt[DDIM * 16];          // x transposed [k][b]

// ---------------- packed f32x2 helpers ----------------
__device__ __forceinline__ ull dup2(float v) {
    ull r; asm("mov.b64 %0, {%1, %1};" : "=l"(r) : "f"(v)); return r;
}
__device__ __forceinline__ ull pack2(float a, float b) {
    ull r; asm("mov.b64 %0, {%1, %2};" : "=l"(r) : "f"(a), "f"(b)); return r;
}
__device__ __forceinline__ void fma2(ull& d, ull a, ull b) {
    asm("fma.rn.f32x2 %0, %1, %2, %0;" : "+l"(d) : "l"(a), "l"(b));
}
__device__ __forceinline__ void unpack2(ull v, float& lo, float& hi) {
    asm("mov.b64 {%0, %1}, %2;" : "=f"(lo), "=f"(hi) : "l"(v));
}

// ---------------- K0: zero slot buffers + transpose x ----------------
#define Z_CP (NSLOT * 16 * NPAD / 4)   // 641024
#define Z_IP (NSLOT * NPAD / 4)        // 40064
#define Z_MP (NSLOT * 16 * DDIM / 4)   // 196608
#define Z_TOT (Z_CP + Z_IP + Z_MP)

__global__ __launch_bounds__(256) void kzero(const float* __restrict__ x) {
    int i = blockIdx.x * 256 + threadIdx.x;
    float4 z = make_float4(0.f, 0.f, 0.f, 0.f);
    if (i < Z_CP)                ((float4*)g_cp)[i] = z;
    else if (i < Z_CP + Z_IP)    ((float4*)g_ip)[i - Z_CP] = z;
    else if (i < Z_TOT)          ((float4*)g_mp)[i - Z_CP - Z_IP] = z;
    if (i < DDIM * 16) {         // g_xt[k*16+b] = x[b*3072+k]
        int b = i & 15, k = i >> 4;
        g_xt[i] = x[b * DDIM + k];
    }
}

// ---------------- K1: cross[b][n] = x[b].img[n], ||img_n||^2 ----------------
// 148 CTAs x 512 thr. Item = (n-tile 512, k-chunk 16), tile-major.
// Stage img block [512 x 16] in smem (coalesced), xt slice [16 x 16b] in smem.
// Thread t computes row n = tile*512 + t, all 16 b as 8 f32x2 accumulators.
__global__ __launch_bounds__(512) void k1(const float* __restrict__ img) {
    __shared__ float xs[512 * XS_STRIDE];   // 40KB
    __shared__ float xt_s[256];             // 1KB: [kk][b]
    const int t = threadIdx.x, c = blockIdx.x;
    const int lo = c * K1_ITEMS / GRID;
    const int hi = (c + 1) * K1_ITEMS / GRID;
    const int slot = c & (NSLOT - 1);
    const int lrr = t >> 2, lcol = t & 3;   // loader: row-group, col (float4)

    ull acc[8];
    ull qac = 0ULL;
#pragma unroll
    for (int j = 0; j < 8; j++) acc[j] = 0ULL;
    int cur = lo / K1_KCH;

    float4 buf[4];
    float xv = 0.f;
    const float4 z4 = make_float4(0.f, 0.f, 0.f, 0.f);

    // prefetch first item
    {
        int tile = lo / K1_KCH, ch = lo - tile * K1_KCH;
#pragma unroll
        for (int r = 0; r < 4; r++) {
            int n = tile * 512 + lrr + 128 * r;
            buf[r] = (n < NPTS)
                ? *(const float4*)(img + (size_t)n * DDIM + ch * 16 + lcol * 4) : z4;
        }
        if (t < 256) xv = g_xt[ch * 256 + t];
    }

    for (int w = lo; w < hi; w++) {
        int tile = w / K1_KCH;
        if (tile != cur) {
            int n = cur * 512 + t;
            if (n < NPTS) {
#pragma unroll
                for (int bp = 0; bp < 8; bp++) {
                    float l, h; unpack2(acc[bp], l, h);
                    g_cp[(slot * 16 + 2 * bp) * NPAD + n] = l;
                    g_cp[(slot * 16 + 2 * bp + 1) * NPAD + n] = h;
                }
                float ql, qh; unpack2(qac, ql, qh);
                g_ip[slot * NPAD + n] = ql + qh;
            }
#pragma unroll
            for (int j = 0; j < 8; j++) acc[j] = 0ULL;
            qac = 0ULL;
            cur = tile;
        }
        __syncthreads();   // previous item's smem reads done
#pragma unroll
        for (int r = 0; r < 4; r++)
            *(float4*)(xs + (lrr + 128 * r) * XS_STRIDE + lcol * 4) = buf[r];
        if (t < 256) xt_s[t] = xv;
        __syncthreads();
        // prefetch next item (overlaps compute below)
        if (w + 1 < hi) {
            int tile2 = (w + 1) / K1_KCH, ch2 = (w + 1) - tile2 * K1_KCH;
#pragma unroll
            for (int r = 0; r < 4; r++) {
                int n = tile2 * 512 + lrr + 128 * r;
                buf[r] = (n < NPTS)
                    ? *(const float4*)(img + (size_t)n * DDIM + ch2 * 16 + lcol * 4) : z4;
            }
            if (t < 256) xv = g_xt[ch2 * 256 + t];
        }
        // compute: 16 k steps, 16 b
#pragma unroll
        for (int q = 0; q < 4; q++) {
            float4 iv = *(const float4*)(xs + t * XS_STRIDE + q * 4);
            ull pxy = pack2(iv.x, iv.y), pzw = pack2(iv.z, iv.w);
            fma2(qac, pxy, pxy);
            fma2(qac, pzw, pzw);
#pragma unroll
            for (int kk = 0; kk < 4; kk++) {
                float f = (&iv.x)[kk];
                ull dv = dup2(f);
                const ulonglong2* xr = (const ulonglong2*)(xt_s + (q * 4 + kk) * 16);
#pragma unroll
                for (int j = 0; j < 4; j++) {
                    ulonglong2 u = xr[j];
                    fma2(acc[2 * j],     u.x, dv);
                    fma2(acc[2 * j + 1], u.y, dv);
                }
            }
        }
    }
    // final flush
    {
        int n = cur * 512 + t;
        if (n < NPTS) {
#pragma unroll
            for (int bp = 0; bp < 8; bp++) {
                float l, h; unpack2(acc[bp], l, h);
                g_cp[(slot * 16 + 2 * bp) * NPAD + n] = l;
                g_cp[(slot * 16 + 2 * bp + 1) * NPAD + n] = h;
            }
            float ql, qh; unpack2(qac, ql, qh);
            g_ip[slot * NPAD + n] = ql + qh;
        }
    }
}

// ---------------- K2a: combine slots -> logits ----------------
__global__ __launch_bounds__(256) void k2a(const float* __restrict__ sval) {
    int idx = blockIdx.x * 256 + threadIdx.x;
    if (idx >= 16 * (NPAD / 4)) return;
    int b = idx / (NPAD / 4);
    int i = idx - b * (NPAD / 4);
    const float s0 = sval[0];
    const float at = sqrtf(1.f - s0);
    const float c1 = at / s0;
    const float c2 = -(at * at) / (2.f * s0);
    float4 cv = make_float4(0.f, 0.f, 0.f, 0.f);
    float4 qv = make_float4(0.f, 0.f, 0.f, 0.f);
#pragma unroll
    for (int s = 0; s < NSLOT; s++) {
        float4 u = *(const float4*)(g_cp + (size_t)(s * 16 + b) * NPAD + 4 * i);
        cv.x += u.x; cv.y += u.y; cv.z += u.z; cv.w += u.w;
        float4 v = *(const float4*)(g_ip + (size_t)s * NPAD + 4 * i);
        qv.x += v.x; qv.y += v.y; qv.z += v.z; qv.w += v.w;
    }
    float4 o;
    o.x = fmaf(c1, cv.x, c2 * qv.x);
    o.y = fmaf(c1, cv.y, c2 * qv.y);
    o.z = fmaf(c1, cv.z, c2 * qv.z);
    o.w = fmaf(c1, cv.w, c2 * qv.w);
    *(float4*)(g_lg + (size_t)b * NPAD + 4 * i) = o;
}

// ---------------- K2b: softmax per b, write packed w[n][b] ----------------
__global__ __launch_bounds__(256) void k2b() {
    const int t = threadIdx.x, b = blockIdx.x;
    __shared__ float rbuf[8];
    __shared__ float bc;

    float4 av[10];
    float m = -1e30f;
    int it = 0;
    for (int i = t; i < 2500; i += 256, it++) {
        float4 a = *(const float4*)(g_lg + (size_t)b * NPAD + 4 * i);
        av[it] = a;
        m = fmaxf(m, fmaxf(fmaxf(a.x, a.y), fmaxf(a.z, a.w)));
    }
    const int nit = it;
    for (int o = 16; o; o >>= 1) m = fmaxf(m, __shfl_xor_sync(0xffffffffu, m, o));
    if ((t & 31) == 0) rbuf[t >> 5] = m;
    __syncthreads();
    if (t == 0) {
        float v = rbuf[0];
        for (int wv = 1; wv < 8; wv++) v = fmaxf(v, rbuf[wv]);
        bc = v;
    }
    __syncthreads();
    const float M = bc;
    __syncthreads();

    const float L2E = 1.44269504088896340736f;
    float sm = 0.f;
    for (int j = 0; j < nit; j++) {
        float4 a = av[j];
        a.x = exp2f((a.x - M) * L2E);
        a.y = exp2f((a.y - M) * L2E);
        a.z = exp2f((a.z - M) * L2E);
        a.w = exp2f((a.w - M) * L2E);
        av[j] = a;
        sm += a.x + a.y + a.z + a.w;
    }
    for (int o = 16; o; o >>= 1) sm += __shfl_xor_sync(0xffffffffu, sm, o);
    if ((t & 31) == 0) rbuf[t >> 5] = sm;
    __syncthreads();
    if (t == 0) {
        float v = 0.f;
        for (int wv = 0; wv < 8; wv++) v += rbuf[wv];
        bc = v;
    }
    __syncthreads();
    const float inv = 1.f / bc;

    it = 0;
    for (int i = t; i < 2500; i += 256, it++) {
        float4 a = av[it];
        int n = 4 * i;
        g_w[(n + 0) * 16 + b] = a.x * inv;
        g_w[(n + 1) * 16 + b] = a.y * inv;
        g_w[(n + 2) * 16 + b] = a.z * inv;
        g_w[(n + 3) * 16 + b] = a.w * inv;
    }
}

// ---------------- K3: mix[b][d] = sum_n w[n][b] img[n][d] ----------------
// 148 CTAs x 512 thr: dt=t&7 (d-quad), bh=(t>>3)&1 (b-half), p=t>>4 (n-partition).
// acc[bp][d] = f32x2 over b=(bh*8+2bp, +1); groups of 4 n-steps for MLP.
__device__ __forceinline__ void k3_flush(ull (&acc)[4][4], float* red, int t,
                                         int slot, int tile) {
#pragma unroll 1
    for (int bp = 0; bp < 4; bp++) {
        __syncthreads();
#pragma unroll
        for (int d = 0; d < 4; d++) {
            float l, h; unpack2(acc[bp][d], l, h);
            red[(2 * d + 0) * 544 + t] = l;
            red[(2 * d + 1) * 544 + t] = h;
        }
        __syncthreads();
        if (t < 128) {
            int h = t & 1, d = (t >> 1) & 3, dq = (t >> 3) & 7, b2 = (t >> 6) & 1;
            float s = 0.f;
#pragma unroll
            for (int pp = 0; pp < 32; pp++)
                s += red[(2 * d + h) * 544 + pp * 16 + b2 * 8 + dq];
            int b = b2 * 8 + bp * 2 + h;
            g_mp[(slot * 16 + b) * DDIM + tile * 32 + dq * 4 + d] = s;
        }
    }
}

__global__ __launch_bounds__(512) void k3(const float* __restrict__ img) {
    __shared__ float red[8 * 544];   // 17.4KB
    const int t = threadIdx.x, c = blockIdx.x;
    const int lo = c * K3_ITEMS / GRID;
    const int hi = (c + 1) * K3_ITEMS / GRID;
    const int slot = c & (NSLOT - 1);
    const int dt = t & 7, bh = (t >> 3) & 1, p = t >> 4;

    ull acc[4][4];
#pragma unroll
    for (int i = 0; i < 4; i++)
#pragma unroll
        for (int j = 0; j < 4; j++) acc[i][j] = 0ULL;

    int cur = lo / K3_NCH;
    for (int w = lo; w < hi; w++) {
        int tile = w / K3_NCH, ch = w - tile * K3_NCH;
        if (tile != cur) {
            k3_flush(acc, red, t, slot, cur);
#pragma unroll
            for (int i = 0; i < 4; i++)
#pragma unroll
                for (int j = 0; j < 4; j++) acc[i][j] = 0ULL;
            cur = tile;
        }
        const int dbase = tile * 32 + dt * 4;
        const int nb = ch * 1000;
        // 7 groups of 4 n-steps: front-batched loads (MLP=12)
        for (int g = 0; g < 7; g++) {
            int n0 = nb + p + 128 * g;
            float4 iv[4];
            ulonglong2 wa[4], wb[4];
#pragma unroll
            for (int j = 0; j < 4; j++) {
                int n = n0 + 32 * j;
                iv[j] = *(const float4*)(img + (size_t)n * DDIM + dbase);
                const float* wr = g_w + (size_t)n * 16 + bh * 8;
                wa[j] = *(const ulonglong2*)(wr);
                wb[j] = *(const ulonglong2*)(wr + 4);
            }
#pragma unroll
            for (int j = 0; j < 4; j++) {
#pragma unroll
                for (int d = 0; d < 4; d++) {
                    ull dv = dup2((&iv[j].x)[d]);
                    fma2(acc[0][d], wa[j].x, dv);
                    fma2(acc[1][d], wa[j].y, dv);
                    fma2(acc[2][d], wb[j].x, dv);
                    fma2(acc[3][d], wb[j].y, dv);
                }
            }
        }
        // tail steps 28..31 (1000 = 31*32 + 8)
#pragma unroll
        for (int s = 28; s < 32; s++) {
            int n = nb + p + 32 * s;
            if (n < nb + 1000) {
                float4 iv = *(const float4*)(img + (size_t)n * DDIM + dbase);
                const float* wr = g_w + (size_t)n * 16 + bh * 8;
                ulonglong2 ua = *(const ulonglong2*)(wr);
                ulonglong2 ub = *(const ulonglong2*)(wr + 4);
#pragma unroll
                for (int d = 0; d < 4; d++) {
                    ull dv = dup2((&iv.x)[d]);
                    fma2(acc[0][d], ua.x, dv);
                    fma2(acc[1][d], ua.y, dv);
                    fma2(acc[2][d], ub.x, dv);
                    fma2(acc[3][d], ub.y, dv);
                }
            }
        }
    }
    k3_flush(acc, red, t, slot, cur);
}

// ---------------- K4: out = (at*mix - x)/bt2 ----------------
__global__ __launch_bounds__(256) void k4(const float* __restrict__ x,
                                          const float* __restrict__ sval,
                                          float* __restrict__ out) {
    int i = blockIdx.x * 256 + threadIdx.x;
    if (i >= 16 * DDIM) return;
    const float s0 = sval[0];
    const float at = sqrtf(1.f - s0);
    float mix = 0.f;
#pragma unroll
    for (int s = 0; s < NSLOT; s++) mix += g_mp[s * 16 * DDIM + i];
    out[i] = (at * mix - x[i]) / s0;
}

// ---------------- launch ----------------
extern "C" void kernel_launch(void* const* d_in, const int* in_sizes, int n_in,
                              void* d_out, int out_size) {
    const float* x    = (const float*)d_in[0];
    const float* img  = (const float*)d_in[1];
    const float* sval = (const float*)d_in[2];
    float* out = (float*)d_out;

    kzero<<<(Z_TOT + 255) / 256, 256>>>(x);
    k1<<<GRID, 512>>>(img);
    k2a<<<(16 * (NPAD / 4) + 255) / 256, 256>>>(sval);
    k2b<<<16, 256>>>();
    k3<<<GRID, 512>>>(img);
    k4<<<(16 * DDIM + 255) / 256, 256>>>(x, sval, out);
}

// round 4
// speedup vs baseline: 1.7886x; 1.2842x over previous
#include <cuda_runtime.h>
#include <cuda_bf16.h>
#include <cstdint>

typedef unsigned long long ull;

#define NPTS  10000
#define NPAD  10016
#define DDIM  3072

// ---------------- device scratch ----------------
__device__ __align__(16) float g_cp[4 * 16 * NPAD];   // cross partials [kq][b][n]
__device__ __align__(16) float g_ip[4 * NPAD];        // ||img||^2 partials [kq][n]
__device__ __align__(16) float g_lg[16 * NPAD];       // logits [b][n]
__device__ __align__(16) float g_w [NPAD * 16];       // unnormalized weights [n][b]
__device__ __align__(16) float g_mp[4 * 16 * DDIM];   // mix partials [quarter][b][d]
__device__ __align__(16) float g_xt[DDIM * 16];       // x transposed [k][b]
__device__ float g_pmax[16 * 8];                      // partial max [b][seg]
__device__ float g_psum[16 * 128];                    // partial sums [b][cta]
__device__ float g_c[4];                              // at, bt2, c1, c2

// ---------------- packed f32x2 helpers ----------------
__device__ __forceinline__ ull dup2(float v) {
    ull r; asm("mov.b64 %0, {%1, %1};" : "=l"(r) : "f"(v)); return r;
}
__device__ __forceinline__ void fma2(ull& d, ull a, ull b) {
    asm("fma.rn.f32x2 %0, %1, %2, %0;" : "+l"(d) : "l"(a), "l"(b));
}
__device__ __forceinline__ void unpack2(ull v, float& lo, float& hi) {
    asm("mov.b64 {%0, %1}, %2;" : "=f"(lo), "=f"(hi) : "l"(v));
}

// ---------------- L0: constants (launch 0) ----------------
__global__ void kconst(const float* __restrict__ sval) {
    if (threadIdx.x == 0) {
        float s = sval[0];
        float at = sqrtf(1.f - s);
        g_c[0] = at;
        g_c[1] = s;                        // bt2
        g_c[2] = at / s;                   // c1
        g_c[3] = -(at * at) / (2.f * s);   // c2
    }
}

// ---------------- L1/L2: transpose x (launches 1,2) ----------------
__global__ __launch_bounds__(256) void ktr(const float* __restrict__ x, int off) {
    int i = off + blockIdx.x * 256 + threadIdx.x;   // i = k*16 + b
    if (i < DDIM * 16) {
        int b = i & 15, k = i >> 4;
        g_xt[i] = x[b * DDIM + k];
    }
}

// ---------------- L3: k1  cross + isq (628 CTAs x 256) ----------------
// CTA c: n-tile = c>>2 (64 rows), k-quarter kq = c&3 (768 k). 24 chunks of 32 k.
// Thread (n_l = t&63, kp = t>>6): 8 k per chunk, all 16 b as 8 f32x2 accs.
__global__ __launch_bounds__(256) void k1(const float* __restrict__ img) {
    __shared__ float sbuf[2][64 * 32];   // 2 x 8KB, XOR-swizzled rows of 128B
    __shared__ float xts[2][32 * 16];    // 2 x 2KB
    __shared__ float2 red[256];

    const int t = threadIdx.x, c = blockIdx.x;
    const int tile = c >> 2, kq = c & 3;
    const int n0 = tile * 64, k0 = kq * 768;
    const int n_l = t & 63, kp = t >> 6;
    const int lrow = t >> 3, lc4 = t & 7;
    const int rA = n0 + lrow, rB = n0 + lrow + 32;
    const int swA = lrow * 32 + ((lc4 ^ (lrow & 7)) << 2);
    const int swB = (lrow + 32) * 32 + ((lc4 ^ (lrow & 7)) << 2);
    const float4 z4 = make_float4(0.f, 0.f, 0.f, 0.f);

    ull acc[8];
#pragma unroll
    for (int j = 0; j < 8; j++) acc[j] = 0ULL;
    float isq = 0.f;

    float4 pA, pB, pX = z4;
    // prefetch + stage chunk 0
    {
        int kk0 = k0;
        pA = (rA < NPTS) ? *(const float4*)(img + (size_t)rA * DDIM + kk0 + lc4 * 4) : z4;
        pB = (rB < NPTS) ? *(const float4*)(img + (size_t)rB * DDIM + kk0 + lc4 * 4) : z4;
        if (t < 128) pX = ((const float4*)(g_xt + (size_t)kk0 * 16))[t];
        *(float4*)&sbuf[0][swA] = pA;
        *(float4*)&sbuf[0][swB] = pB;
        if (t < 128) ((float4*)xts[0])[t] = pX;
    }
    __syncthreads();

    const int p0 = n_l * 32 + (((2 * kp) ^ (n_l & 7)) << 2);
    const int p1 = n_l * 32 + (((2 * kp + 1) ^ (n_l & 7)) << 2);
    const int xo = kp * 8 * 16;

    for (int ch = 0; ch < 24; ch++) {
        const int s = ch & 1;
        if (ch + 1 < 24) {   // prefetch next chunk (overlaps compute)
            int kk0 = k0 + (ch + 1) * 32;
            pA = (rA < NPTS) ? *(const float4*)(img + (size_t)rA * DDIM + kk0 + lc4 * 4) : z4;
            pB = (rB < NPTS) ? *(const float4*)(img + (size_t)rB * DDIM + kk0 + lc4 * 4) : z4;
            if (t < 128) pX = ((const float4*)(g_xt + (size_t)kk0 * 16))[t];
        }
        // compute on buffer s
        const float* sb = sbuf[s];
        const float* xt = xts[s];
        float4 v0 = *(const float4*)&sb[p0];
        float4 v1 = *(const float4*)&sb[p1];
        float fv[8] = { v0.x, v0.y, v0.z, v0.w, v1.x, v1.y, v1.z, v1.w };
#pragma unroll
        for (int kk = 0; kk < 8; kk++) {
            float f = fv[kk];
            isq = fmaf(f, f, isq);
            ull dv = dup2(f);
            const ulonglong2* xr = (const ulonglong2*)(xt + xo + kk * 16);
#pragma unroll
            for (int j = 0; j < 4; j++) {
                ulonglong2 u = xr[j];
                fma2(acc[2 * j],     u.x, dv);
                fma2(acc[2 * j + 1], u.y, dv);
            }
        }
        __syncthreads();
        if (ch + 1 < 24) {
            *(float4*)&sbuf[s ^ 1][swA] = pA;
            *(float4*)&sbuf[s ^ 1][swB] = pB;
            if (t < 128) ((float4*)xts[s ^ 1])[t] = pX;
            __syncthreads();
        }
    }

    // epilogue: reduce over kp (threads n_l, n_l+64, n_l+128, n_l+192)
#pragma unroll 1
    for (int bp = 0; bp < 8; bp++) {
        __syncthreads();
        float lo, hi; unpack2(acc[bp], lo, hi);
        red[t] = make_float2(lo, hi);
        __syncthreads();
        if (t < 64) {
            float2 s0 = red[t], s1 = red[t + 64], s2 = red[t + 128], s3 = red[t + 192];
            float sx = s0.x + s1.x + s2.x + s3.x;
            float sy = s0.y + s1.y + s2.y + s3.y;
            int n = n0 + t;
            if (n < NPTS) {
                g_cp[(kq * 16 + 2 * bp) * NPAD + n] = sx;
                g_cp[(kq * 16 + 2 * bp + 1) * NPAD + n] = sy;
            }
        }
    }
    __syncthreads();
    ((float*)red)[t] = isq;
    __syncthreads();
    if (t < 64) {
        const float* r = (const float*)red;
        float s = r[t] + r[t + 64] + r[t + 128] + r[t + 192];
        int n = n0 + t;
        if (n < NPTS) g_ip[kq * NPAD + n] = s;
    }
}

// ---------------- L4: s1  logits + partial max (128 CTAs) ----------------
__global__ __launch_bounds__(256) void s1() {
    const int t = threadIdx.x, c = blockIdx.x;
    const int b = c >> 3, seg = c & 7;
    const float c1 = g_c[2], c2 = g_c[3];
    const int nbase = seg * 1252;
    const int nend = min(nbase + 1252, NPTS);
    float m = -1e30f;
    for (int i = nbase + t; i < nend; i += 256) {
        float cr = g_cp[b * NPAD + i] + g_cp[(16 + b) * NPAD + i]
                 + g_cp[(32 + b) * NPAD + i] + g_cp[(48 + b) * NPAD + i];
        float qq = g_ip[i] + g_ip[NPAD + i] + g_ip[2 * NPAD + i] + g_ip[3 * NPAD + i];
        float lg = fmaf(c1, cr, c2 * qq);
        g_lg[b * NPAD + i] = lg;
        m = fmaxf(m, lg);
    }
    __shared__ float wm[8];
    for (int o = 16; o; o >>= 1) m = fmaxf(m, __shfl_xor_sync(0xffffffffu, m, o));
    if ((t & 31) == 0) wm[t >> 5] = m;
    __syncthreads();
    if (t == 0) {
        float v = wm[0];
        for (int w = 1; w < 8; w++) v = fmaxf(v, wm[w]);
        g_pmax[c] = v;
    }
}

// ---------------- L5: s3  exp + unnormalized w + partial sums (128 CTAs) ----------------
__global__ __launch_bounds__(256) void s3() {
    const int t = threadIdx.x, c = blockIdx.x;
    const int bb = t & 15, nn = t >> 4;
    const float L2E = 1.44269504088896340736f;
    float M = g_pmax[bb * 8];
#pragma unroll
    for (int s = 1; s < 8; s++) M = fmaxf(M, g_pmax[bb * 8 + s]);
    const int base = c * 79;
    float sum = 0.f;
#pragma unroll
    for (int r = 0; r < 5; r++) {
        int n = base + nn + 16 * r;
        if (n < base + 79 && n < NPTS) {
            float e = exp2f((g_lg[bb * NPAD + n] - M) * L2E);
            g_w[n * 16 + bb] = e;
            sum += e;
        }
    }
    sum += __shfl_xor_sync(0xffffffffu, sum, 16);
    __shared__ float sm[8 * 16];
    if ((t & 31) < 16) sm[(t >> 5) * 16 + bb] = sum;
    __syncthreads();
    if (t < 16) {
        float s = 0.f;
        for (int w = 0; w < 8; w++) s += sm[w * 16 + t];
        g_psum[t * 128 + c] = s;
    }
}

// ---------------- L6: k3  mix partials (384 CTAs x 256) ----------------
// CTA c: d-tile = c>>2 (32 cols), quarter = c&3 (2500 n). Thread: dt=t&7 (4 cols),
// bh=(t>>3)&1 (8 b), p=t>>4 (16-way n partition). acc[bp][d] f32x2.
__global__ __launch_bounds__(256) void k3(const float* __restrict__ img) {
    __shared__ float red[256 * 8];
    const int t = threadIdx.x, c = blockIdx.x;
    const int dtile = c >> 2, quarter = c & 3;
    const int dt = t & 7, bh = (t >> 3) & 1, p = t >> 4;
    const int dbase = dtile * 32 + dt * 4;
    const int q0 = quarter * 2500;

    ull acc[4][4];
#pragma unroll
    for (int i = 0; i < 4; i++)
#pragma unroll
        for (int j = 0; j < 4; j++) acc[i][j] = 0ULL;

#pragma unroll 1
    for (int j = 0; j < 156; j += 2) {
        int n1 = q0 + p + 16 * j, n2 = n1 + 16;
        float4 i1 = *(const float4*)(img + (size_t)n1 * DDIM + dbase);
        float4 i2 = *(const float4*)(img + (size_t)n2 * DDIM + dbase);
        ulonglong2 wa1 = *(const ulonglong2*)(g_w + (size_t)n1 * 16 + bh * 8);
        ulonglong2 wb1 = *(const ulonglong2*)(g_w + (size_t)n1 * 16 + bh * 8 + 4);
        ulonglong2 wa2 = *(const ulonglong2*)(g_w + (size_t)n2 * 16 + bh * 8);
        ulonglong2 wb2 = *(const ulonglong2*)(g_w + (size_t)n2 * 16 + bh * 8 + 4);
#pragma unroll
        for (int d = 0; d < 4; d++) {
            ull dv = dup2((&i1.x)[d]);
            fma2(acc[0][d], wa1.x, dv);
            fma2(acc[1][d], wa1.y, dv);
            fma2(acc[2][d], wb1.x, dv);
            fma2(acc[3][d], wb1.y, dv);
        }
#pragma unroll
        for (int d = 0; d < 4; d++) {
            ull dv = dup2((&i2.x)[d]);
            fma2(acc[0][d], wa2.x, dv);
            fma2(acc[1][d], wa2.y, dv);
            fma2(acc[2][d], wb2.x, dv);
            fma2(acc[3][d], wb2.y, dv);
        }
    }
    // tail: n = q0+2496..2499 handled by p<4
    if (p < 4) {
        int n = q0 + 2496 + p;
        float4 i1 = *(const float4*)(img + (size_t)n * DDIM + dbase);
        ulonglong2 wa = *(const ulonglong2*)(g_w + (size_t)n * 16 + bh * 8);
        ulonglong2 wb = *(const ulonglong2*)(g_w + (size_t)n * 16 + bh * 8 + 4);
#pragma unroll
        for (int d = 0; d < 4; d++) {
            ull dv = dup2((&i1.x)[d]);
            fma2(acc[0][d], wa.x, dv);
            fma2(acc[1][d], wa.y, dv);
            fma2(acc[2][d], wb.x, dv);
            fma2(acc[3][d], wb.y, dv);
        }
    }

    // reduce over p (16) per (b, col)
#pragma unroll 1
    for (int bp = 0; bp < 4; bp++) {
        __syncthreads();
#pragma unroll
        for (int d = 0; d < 4; d++) {
            float lo, hi; unpack2(acc[bp][d], lo, hi);
            red[t * 8 + 2 * d] = lo;
            red[t * 8 + 2 * d + 1] = hi;
        }
        __syncthreads();
        if (t < 128) {
            int h = t & 1, d = (t >> 1) & 3, dtw = (t >> 3) & 7, bhw = t >> 6;
            float s = 0.f;
#pragma unroll
            for (int p2 = 0; p2 < 16; p2++)
                s += red[(dtw + bhw * 8 + p2 * 16) * 8 + 2 * d + h];
            int b = bhw * 8 + bp * 2 + h;
            g_mp[(quarter * 16 + b) * DDIM + dtile * 32 + dtw * 4 + d] = s;
        }
    }
}

// ---------------- L7: k4  combine + normalize + final (48 CTAs x 256) ----------------
__global__ __launch_bounds__(256) void k4(const float* __restrict__ x,
                                          float* __restrict__ out) {
    const int t = threadIdx.x, c = blockIdx.x;
    const int blo = (c * 1024) / DDIM;
    const int bhi = ((c + 1) * 1024 - 1) / DDIM;
    __shared__ float wsum[8];
    __shared__ float invs[2];
    {
        int myb = (t < 128) ? blo : bhi;
        float s = g_psum[myb * 128 + (t & 127)];
        for (int o = 16; o; o >>= 1) s += __shfl_xor_sync(0xffffffffu, s, o);
        if ((t & 31) == 0) wsum[t >> 5] = s;
    }
    __syncthreads();
    if (t == 0)   invs[0] = 1.f / (wsum[0] + wsum[1] + wsum[2] + wsum[3]);
    if (t == 128) invs[1] = 1.f / (wsum[4] + wsum[5] + wsum[6] + wsum[7]);
    __syncthreads();

    const float at = g_c[0], bt2 = g_c[1];
    int i = (c * 256 + t) * 4;
    int b = i / DDIM;
    int d = i - b * DDIM;
    float inv = (b == blo) ? invs[0] : invs[1];
    float4 m0 = *(const float4*)(g_mp + (size_t)b * DDIM + d);
    float4 m1 = *(const float4*)(g_mp + (size_t)(16 + b) * DDIM + d);
    float4 m2 = *(const float4*)(g_mp + (size_t)(32 + b) * DDIM + d);
    float4 m3 = *(const float4*)(g_mp + (size_t)(48 + b) * DDIM + d);
    float4 xv = *(const float4*)(x + i);
    float sc = at * inv / bt2;
    float4 o;
    o.x = sc * (m0.x + m1.x + m2.x + m3.x) - xv.x / bt2;
    o.y = sc * (m0.y + m1.y + m2.y + m3.y) - xv.y / bt2;
    o.z = sc * (m0.z + m1.z + m2.z + m3.z) - xv.z / bt2;
    o.w = sc * (m0.w + m1.w + m2.w + m3.w) - xv.w / bt2;
    *(float4*)(out + i) = o;
}

// ---------------- launch ----------------
extern "C" void kernel_launch(void* const* d_in, const int* in_sizes, int n_in,
                              void* d_out, int out_size) {
    const float* x    = (const float*)d_in[0];
    const float* img  = (const float*)d_in[1];
    const float* sval = (const float*)d_in[2];
    float* out = (float*)d_out;

    kconst<<<1, 32>>>(sval);                 // 0
    ktr<<<96, 256>>>(x, 0);                  // 1  (k < 1536)
    ktr<<<96, 256>>>(x, 24576);              // 2  (k >= 1536)
    k1<<<628, 256>>>(img);                   // 3  <- ncu capture lands here
    s1<<<128, 256>>>();                      // 4
    s3<<<128, 256>>>();                      // 5
    k3<<<384, 256>>>(img);                   // 6
    k4<<<48, 256>>>(x, out);                 // 7
}